// round 12
// baseline (speedup 1.0000x reference)
#include <cuda_runtime.h>
#include <cuda_bf16.h>
#include <math.h>
#include <stdint.h>

#define NPTS 100000
#define KNB  16
#define DIM  64
#define NK   (NPTS*KNB)

typedef unsigned long long ull;

// ---------------- f32x2 helpers (frontend) ----------------
__device__ __forceinline__ ull ffma2(ull a, ull b, ull c) {
    ull d;
    asm("fma.rn.f32x2 %0, %1, %2, %3;" : "=l"(d) : "l"(a), "l"(b), "l"(c));
    return d;
}
__device__ __forceinline__ void unpack2(ull p, float& lo, float& hi) {
    asm("mov.b64 {%0, %1}, %2;" : "=f"(lo), "=f"(hi) : "l"(p));
}

// ---------------- mma helpers ----------------
__device__ __forceinline__ uint32_t smem_u32(const void* p) {
    uint32_t a;
    asm("{ .reg .u64 t; cvta.to.shared.u64 t, %1; cvt.u32.u64 %0, t; }" : "=r"(a) : "l"(p));
    return a;
}
__device__ __forceinline__ void ldsm_x4(uint32_t* r, uint32_t addr) {
    asm volatile("ldmatrix.sync.aligned.m8n8.x4.shared.b16 {%0,%1,%2,%3}, [%4];"
        : "=r"(r[0]), "=r"(r[1]), "=r"(r[2]), "=r"(r[3]) : "r"(addr));
}
__device__ __forceinline__ void mma16816(float* d, const uint32_t* a, const uint32_t* b) {
    asm volatile("mma.sync.aligned.m16n8k16.row.col.f32.bf16.bf16.f32 "
        "{%0,%1,%2,%3}, {%4,%5,%6,%7}, {%8,%9}, {%0,%1,%2,%3};"
        : "+f"(d[0]), "+f"(d[1]), "+f"(d[2]), "+f"(d[3])
        : "r"(a[0]), "r"(a[1]), "r"(a[2]), "r"(a[3]), "r"(b[0]), "r"(b[1]));
}
#define SWZ(o) ((o) ^ (((o) >> 3) & 0x70))

// ---------------- scratch ----------------
__device__ float  g_q[(size_t)NPTS*DIM];
__device__ float  g_k[(size_t)NPTS*DIM];
__device__ float  g_v[(size_t)NPTS*DIM];
__device__ float  g_wpre[(size_t)NPTS*KNB*DIM];
__device__ double g_acc[256];
__device__ float  g_stats[256];

__global__ void zero_acc_kernel() {
    if (threadIdx.x < 256) g_acc[threadIdx.x] = 0.0;
}

// ---------------- frontend: qkv GEMM + BN1 stats ----------------
// FE_BLOCKS MUST equal 444 (= 3 CTAs/SM x 148 SM): qkv blocks are persistent,
// so any block beyond the first wave serializes behind the whole kernel.
#define FE_THREADS   192
#define QKV_BLOCKS   304
#define STATS_BLOCKS 140
#define FE_BLOCKS    (QKV_BLOCKS + STATS_BLOCKS)
#define STAT_STRIDE  (STATS_BLOCKS*12)

__global__ void __launch_bounds__(FE_THREADS) frontend_kernel(
    const float* __restrict__ feats,
    const float* __restrict__ qw, const float* __restrict__ qb,
    const float* __restrict__ kw, const float* __restrict__ kb,
    const float* __restrict__ vw, const float* __restrict__ vb,
    const float* __restrict__ points,
    const int*   __restrict__ nb,
    const float* __restrict__ pw,
    const float* __restrict__ pb)
{
    extern __shared__ float sm[];
    const int tid = threadIdx.x;

    if (blockIdx.x < QKV_BLOCKS) {
        float* sW    = sm;
        float* sFdup = sm + 12288;
        float* sB    = sm + 12288 + 2304;

        for (int i = tid; i < 192*64; i += FE_THREADS) {
            int c = i % 192, e = i / 192;
            const float* src = (c < 64) ? qw : (c < 128) ? kw : vw;
            sW[e*192 + c] = __ldg(src + (c & 63)*DIM + e);
        }
        if (tid < 192) {
            const float* src = (tid < 64) ? qb : (tid < 128) ? kb : vb;
            sB[tid] = __ldg(src + (tid & 63));
        }
        __syncthreads();

        const int c4 = tid % 48;
        const int pb4 = tid / 48;
        const int c = 4*c4;
        const ull b0 = *(const ull*)&sB[c];
        const ull b1 = *(const ull*)&sB[c+2];
        float* dst = (c < 64) ? g_q : (c < 128) ? g_k : g_v;
        const int cc = c & 63;

        for (int tile = blockIdx.x; tile < NPTS/16; tile += QKV_BLOCKS) {
            const int n0 = tile*16;
            __syncthreads();
            for (int i = tid; i < 16*64; i += FE_THREADS) {
                int e = i & 63, p = i >> 6;
                float f = __ldg(feats + (size_t)(n0+p)*DIM + e);
                *(float2*)&sFdup[e*36 + 2*p] = make_float2(f, f);
            }
            __syncthreads();

            ull acc[4][2];
            #pragma unroll
            for (int p = 0; p < 4; p++) { acc[p][0] = b0; acc[p][1] = b1; }

            #pragma unroll
            for (int e = 0; e < 64; e++) {
                ulonglong2 wv  = *(const ulonglong2*)&sW[e*192 + c];
                ulonglong2 f01 = *(const ulonglong2*)&sFdup[e*36 + 8*pb4];
                ulonglong2 f23 = *(const ulonglong2*)&sFdup[e*36 + 8*pb4 + 4];
                acc[0][0] = ffma2(f01.x, wv.x, acc[0][0]);
                acc[0][1] = ffma2(f01.x, wv.y, acc[0][1]);
                acc[1][0] = ffma2(f01.y, wv.x, acc[1][0]);
                acc[1][1] = ffma2(f01.y, wv.y, acc[1][1]);
                acc[2][0] = ffma2(f23.x, wv.x, acc[2][0]);
                acc[2][1] = ffma2(f23.x, wv.y, acc[2][1]);
                acc[3][0] = ffma2(f23.y, wv.x, acc[3][0]);
                acc[3][1] = ffma2(f23.y, wv.y, acc[3][1]);
            }

            const int nb0 = n0 + 4*pb4;
            #pragma unroll
            for (int p = 0; p < 4; p++) {
                float4 r;
                unpack2(acc[p][0], r.x, r.y);
                unpack2(acc[p][1], r.z, r.w);
                *(float4*)(dst + (size_t)(nb0+p)*DIM + cc) = r;
            }
        }
    } else {
        // ---------------- stats1: 4 independent rows per iteration ----------------
        const int quad = tid & 15;
        const int slot = tid >> 4;          // 0..11
        const int d0   = 4*quad;

        float w[12], br[4];
        #pragma unroll
        for (int j = 0; j < 4; j++) {
            w[j*3+0] = __ldg(pw + (d0+j)*3 + 0);
            w[j*3+1] = __ldg(pw + (d0+j)*3 + 1);
            w[j*3+2] = __ldg(pw + (d0+j)*3 + 2);
            br[j]    = __ldg(pb + d0 + j);
        }

        float s[4] = {0,0,0,0}, sq[4] = {0,0,0,0};
        const int bid  = blockIdx.x - QKV_BLOCKS;
        const int base = bid*12 + slot;

        for (int r = base; r < NK; r += 4*STAT_STRIDE) {
            float px[4], py[4], pz[4];
            #pragma unroll
            for (int u = 0; u < 4; u++) {
                int rr = r + u*STAT_STRIDE;
                if (rr < NK) {
                    int idx = __ldg(nb + rr);
                    if (idx >= NPTS) { px[u] = py[u] = pz[u] = 1e6f; }
                    else {
                        px[u] = __ldg(points + (size_t)idx*3    );
                        py[u] = __ldg(points + (size_t)idx*3 + 1);
                        pz[u] = __ldg(points + (size_t)idx*3 + 2);
                    }
                } else { px[u] = py[u] = pz[u] = 0.f; }
            }
            #pragma unroll
            for (int u = 0; u < 4; u++) {
                if (r + u*STAT_STRIDE < NK) {
                    #pragma unroll
                    for (int j = 0; j < 4; j++) {
                        float v = fmaf(w[j*3+2], pz[u],
                                  fmaf(w[j*3+1], py[u],
                                  fmaf(w[j*3+0], px[u], br[j])));
                        s[j] += v;
                        sq[j] = fmaf(v, v, sq[j]);
                    }
                }
            }
        }

        float* sred = sm;
        #pragma unroll
        for (int j = 0; j < 4; j++) {
            sred[tid*8 + j]     = s[j];
            sred[tid*8 + 4 + j] = sq[j];
        }
        __syncthreads();
        if (tid < 64) {
            int tq = tid >> 2, j = tid & 3;
            double ds = 0.0, dsq = 0.0;
            #pragma unroll
            for (int sl = 0; sl < 12; sl++) {
                ds  += (double)sred[(sl*16 + tq)*8 + j];
                dsq += (double)sred[(sl*16 + tq)*8 + 4 + j];
            }
            atomicAdd(&g_acc[tid],      ds);
            atomicAdd(&g_acc[64 + tid], dsq);
        }
    }
}

// ---------------- finalize ----------------
__global__ void finalize_kernel(const float* __restrict__ gamma,
                                const float* __restrict__ beta, int base)
{
    int d = threadIdx.x;
    if (d < 64) {
        double cnt = (double)NK;
        double m   = g_acc[base + d] / cnt;
        double var = g_acc[base + 64 + d] / cnt - m*m;
        double rs  = 1.0 / sqrt(var + 1e-5);
        double g   = (double)__ldg(gamma + d);
        g_stats[base + d]      = (float)(rs * g);
        g_stats[base + 64 + d] = (float)((double)__ldg(beta + d) - m * rs * g);
    }
}

// ---------------- pass C: mma.sync bf16 2-term split GEMM (uint4 A-stores) ----
#define OFF_BHI  0
#define OFF_BLO  8192
#define OFF_AHI  16384
#define OFF_ALO  32768
#define OFF_Q    49152
#define OFF_C    51200
#define OFF_WB   52224
#define PC_SMEM  52480
#define PC_BLOCKS 444

__global__ void __launch_bounds__(128) passC_kernel(
    const float* __restrict__ points,
    const int*   __restrict__ nb,
    const float* __restrict__ pw,
    const float* __restrict__ pb,
    const float* __restrict__ ww,
    const float* __restrict__ wb)
{
    extern __shared__ __align__(1024) char smc[];
    const uint32_t sb = smem_u32(smc);
    const int tid  = threadIdx.x;
    const int wid  = tid >> 5;
    const int lane = tid & 31;

    float* sQ  = (float*)(smc + OFF_Q);
    float* sC  = (float*)(smc + OFF_C);
    float* sWb = (float*)(smc + OFF_WB);

    for (int i = tid; i < 4096; i += 128) {
        int d = i >> 6, e = i & 63;
        float v = __ldg(ww + d*DIM + e);
        __nv_bfloat16 h = __float2bfloat16(v);
        float lo = v - __bfloat162float(h);
        uint32_t sw = SWZ((uint32_t)(d*128 + e*2));
        *(__nv_bfloat16*)(smc + OFF_BHI + sw) = h;
        *(__nv_bfloat16*)(smc + OFF_BLO + sw) = __float2bfloat16(lo);
    }
    if (tid < 64) {
        float sc = g_stats[tid], sh = g_stats[64 + tid];
        sC[0*64 + tid] = sc * __ldg(pw + tid*3    );
        sC[1*64 + tid] = sc * __ldg(pw + tid*3 + 1);
        sC[2*64 + tid] = sc * __ldg(pw + tid*3 + 2);
        sC[3*64 + tid] = fmaf(sc, __ldg(pb + tid), sh);
        sWb[tid] = __ldg(wb + tid);
    }
    __syncthreads();

    const int m  = tid;
    const int p  = m >> 4;
    const int kk = m & 15;

    float2 s[8], q2[8];
    #pragma unroll
    for (int nt = 0; nt < 8; nt++) { s[nt] = make_float2(0.f,0.f); q2[nt] = make_float2(0.f,0.f); }

    const int c4 = 2*(lane & 3);
    const int rb = wid*32 + (lane >> 2);

    for (int tile = blockIdx.x; tile < NPTS/8; tile += PC_BLOCKS) {
        __syncwarp();

        {
            int pp = tid >> 4, e4 = (tid & 15) * 4;
            *(float4*)&sQ[pp*64 + e4] =
                *(const float4*)(g_q + (size_t)(tile*8 + pp)*DIM + e4);
        }
        __syncwarp();

        const int n = tile*8 + p;
        int idx = __ldg(nb + (size_t)n*KNB + kk);
        bool pad = (idx >= NPTS);
        float x, y, z;
        if (pad) { x = y = z = 1e6f; }
        else {
            x = __ldg(points + (size_t)idx*3    );
            y = __ldg(points + (size_t)idx*3 + 1);
            z = __ldg(points + (size_t)idx*3 + 2);
        }
        const float* krow = g_k + (size_t)(pad ? 0 : idx)*DIM;

        // build A row m: 8 channels per iteration, uint4 stores
        #pragma unroll
        for (int e0 = 0; e0 < 64; e0 += 8) {
            float4 kgA = pad ? make_float4(0.f,0.f,0.f,0.f) : *(const float4*)(krow + e0);
            float4 kgB = pad ? make_float4(0.f,0.f,0.f,0.f) : *(const float4*)(krow + e0 + 4);
            float win[8];
            #pragma unroll
            for (int half = 0; half < 2; half++) {
                const int e = e0 + 4*half;
                float4 kg = half ? kgB : kgA;
                float4 q4 = *(const float4*)&sQ[p*64 + e];
                float4 cx = *(const float4*)&sC[0*64 + e];
                float4 cy = *(const float4*)&sC[1*64 + e];
                float4 cz = *(const float4*)&sC[2*64 + e];
                float4 cb = *(const float4*)&sC[3*64 + e];
                win[4*half+0] = fmaf(kg.x, q4.x, fmaxf(fmaf(cz.x, z, fmaf(cy.x, y, fmaf(cx.x, x, cb.x))), 0.f));
                win[4*half+1] = fmaf(kg.y, q4.y, fmaxf(fmaf(cz.y, z, fmaf(cy.y, y, fmaf(cx.y, x, cb.y))), 0.f));
                win[4*half+2] = fmaf(kg.z, q4.z, fmaxf(fmaf(cz.z, z, fmaf(cy.z, y, fmaf(cx.z, x, cb.z))), 0.f));
                win[4*half+3] = fmaf(kg.w, q4.w, fmaxf(fmaf(cz.w, z, fmaf(cy.w, y, fmaf(cx.w, x, cb.w))), 0.f));
            }

            __nv_bfloat16 h[8]; float lo[8];
            #pragma unroll
            for (int j = 0; j < 8; j++) {
                h[j]  = __float2bfloat16(win[j]);
                lo[j] = win[j] - __bfloat162float(h[j]);
            }
            uint32_t sw = SWZ((uint32_t)(m*128 + e0*2));   // 16B-aligned
            uint4 hv, lv;
            {
                __nv_bfloat162 t0 = __halves2bfloat162(h[0], h[1]);
                __nv_bfloat162 t1 = __halves2bfloat162(h[2], h[3]);
                __nv_bfloat162 t2 = __halves2bfloat162(h[4], h[5]);
                __nv_bfloat162 t3 = __halves2bfloat162(h[6], h[7]);
                hv = make_uint4(*(uint32_t*)&t0, *(uint32_t*)&t1,
                                *(uint32_t*)&t2, *(uint32_t*)&t3);
                __nv_bfloat162 u0 = __floats2bfloat162_rn(lo[0], lo[1]);
                __nv_bfloat162 u1 = __floats2bfloat162_rn(lo[2], lo[3]);
                __nv_bfloat162 u2 = __floats2bfloat162_rn(lo[4], lo[5]);
                __nv_bfloat162 u3 = __floats2bfloat162_rn(lo[6], lo[7]);
                lv = make_uint4(*(uint32_t*)&u0, *(uint32_t*)&u1,
                                *(uint32_t*)&u2, *(uint32_t*)&u3);
            }
            *(uint4*)(smc + OFF_AHI + sw) = hv;
            *(uint4*)(smc + OFF_ALO + sw) = lv;
        }
        __syncwarp();

        float acc[2][8][4];
        #pragma unroll
        for (int mt = 0; mt < 2; mt++)
            #pragma unroll
            for (int nt = 0; nt < 8; nt++)
                #pragma unroll
                for (int r = 0; r < 4; r++) acc[mt][nt][r] = 0.f;

        #pragma unroll
        for (int ks = 0; ks < 4; ks++) {
            uint32_t ah[2][4], al[2][4];
            #pragma unroll
            for (int mt = 0; mt < 2; mt++) {
                uint32_t off = SWZ((uint32_t)((wid*32 + mt*16 + (lane & 15))*128
                                              + ks*32 + ((lane >> 4) << 4)));
                ldsm_x4(ah[mt], sb + OFF_AHI + off);
                ldsm_x4(al[mt], sb + OFF_ALO + off);
            }
            uint32_t bh[4][4], bl[4][4];
            #pragma unroll
            for (int np = 0; np < 4; np++) {
                int nrow = np*16 + (lane & 7) + ((lane >> 4) << 3);
                uint32_t off = SWZ((uint32_t)(nrow*128 + ks*32 + (((lane >> 3) & 1) << 4)));
                ldsm_x4(bh[np], sb + OFF_BHI + off);
                ldsm_x4(bl[np], sb + OFF_BLO + off);
            }
            #pragma unroll
            for (int mt = 0; mt < 2; mt++)
                #pragma unroll
                for (int np = 0; np < 4; np++) {
                    mma16816(acc[mt][2*np  ], ah[mt], &bh[np][0]);
                    mma16816(acc[mt][2*np  ], al[mt], &bh[np][0]);
                    mma16816(acc[mt][2*np  ], ah[mt], &bl[np][0]);
                    mma16816(acc[mt][2*np+1], ah[mt], &bh[np][2]);
                    mma16816(acc[mt][2*np+1], al[mt], &bh[np][2]);
                    mma16816(acc[mt][2*np+1], ah[mt], &bl[np][2]);
                }
        }

        #pragma unroll
        for (int nt = 0; nt < 8; nt++) {
            float bx = sWb[nt*8 + c4];
            float by = sWb[nt*8 + c4 + 1];
            #pragma unroll
            for (int mt = 0; mt < 2; mt++) {
                float v0 = acc[mt][nt][0] + bx;
                float v1 = acc[mt][nt][1] + by;
                float v2 = acc[mt][nt][2] + bx;
                float v3 = acc[mt][nt][3] + by;
                size_t r0 = (size_t)(tile*128 + rb + mt*16)*64 + nt*8 + c4;
                *(float2*)(g_wpre + r0)        = make_float2(v0, v1);
                *(float2*)(g_wpre + r0 + 512)  = make_float2(v2, v3);
                s[nt].x += v0 + v2;  s[nt].y += v1 + v3;
                q2[nt].x = fmaf(v0, v0, fmaf(v2, v2, q2[nt].x));
                q2[nt].y = fmaf(v1, v1, fmaf(v3, v3, q2[nt].y));
            }
        }
    }

    #pragma unroll
    for (int nt = 0; nt < 8; nt++) {
        #pragma unroll
        for (int d = 4; d <= 16; d <<= 1) {
            s[nt].x  += __shfl_xor_sync(0xFFFFFFFFu, s[nt].x,  d);
            s[nt].y  += __shfl_xor_sync(0xFFFFFFFFu, s[nt].y,  d);
            q2[nt].x += __shfl_xor_sync(0xFFFFFFFFu, q2[nt].x, d);
            q2[nt].y += __shfl_xor_sync(0xFFFFFFFFu, q2[nt].y, d);
        }
    }
    if ((lane >> 2) == 0) {
        #pragma unroll
        for (int nt = 0; nt < 8; nt++) {
            int c = nt*8 + c4;
            atomicAdd(&g_acc[128 + c],     (double)s[nt].x);
            atomicAdd(&g_acc[128 + c + 1], (double)s[nt].y);
            atomicAdd(&g_acc[192 + c],     (double)q2[nt].x);
            atomicAdd(&g_acc[192 + c + 1], (double)q2[nt].y);
        }
    }
}

// ---------------- pass D: warp-per-point, 2 channels/lane, no block syncs ------
#define PD_THREADS 256
#define PD_BLOCKS  1184
__global__ void __launch_bounds__(PD_THREADS) passD_kernel(
    const float* __restrict__ points,
    const int*   __restrict__ nb,
    const float* __restrict__ pw,
    const float* __restrict__ pb,
    float* __restrict__ out)
{
    __shared__ float4 sPts[8*16];

    const int tid  = threadIdx.x;
    const int w    = tid >> 5;
    const int lane = tid & 31;
    const int d0   = 2*lane;

    float cx[2], cy[2], cz[2], cb[2], sc2[2], sh2[2];
    #pragma unroll
    for (int j = 0; j < 2; j++) {
        float sc = g_stats[d0 + j], sh = g_stats[64 + d0 + j];
        cx[j] = sc * __ldg(pw + (d0+j)*3    );
        cy[j] = sc * __ldg(pw + (d0+j)*3 + 1);
        cz[j] = sc * __ldg(pw + (d0+j)*3 + 2);
        cb[j] = fmaf(sc, __ldg(pb + d0 + j), sh);
        sc2[j] = g_stats[128 + d0 + j];
        sh2[j] = g_stats[192 + d0 + j];
    }

    for (int n = blockIdx.x*8 + w; n < NPTS; n += PD_BLOCKS*8) {
        __syncwarp();
        if (lane < KNB) {
            int idx = __ldg(nb + (size_t)n*KNB + lane);
            float4 pt;
            if (idx >= NPTS) {
                pt = make_float4(1e6f, 1e6f, 1e6f, __int_as_float(-1));
            } else {
                pt.x = __ldg(points + (size_t)idx*3    );
                pt.y = __ldg(points + (size_t)idx*3 + 1);
                pt.z = __ldg(points + (size_t)idx*3 + 2);
                pt.w = __int_as_float(idx);
            }
            sPts[w*16 + lane] = pt;
        }
        __syncwarp();

        float2 wq[KNB];
        #pragma unroll
        for (int k = 0; k < KNB; k++) {
            float2 v = *(const float2*)(g_wpre + ((size_t)n*KNB + k)*DIM + d0);
            wq[k].x = fmaxf(fmaf(v.x, sc2[0], sh2[0]), 0.f);
            wq[k].y = fmaxf(fmaf(v.y, sc2[1], sh2[1]), 0.f);
        }
        float2 mx = wq[0];
        #pragma unroll
        for (int k = 1; k < KNB; k++) {
            mx.x = fmaxf(mx.x, wq[k].x);
            mx.y = fmaxf(mx.y, wq[k].y);
        }
        float2 se = make_float2(0.f, 0.f);
        #pragma unroll
        for (int k = 0; k < KNB; k++) {
            wq[k].x = __expf(wq[k].x - mx.x); se.x += wq[k].x;
            wq[k].y = __expf(wq[k].y - mx.y); se.y += wq[k].y;
        }
        float2 inv;
        inv.x = __fdividef(1.f, se.x);
        inv.y = __fdividef(1.f, se.y);

        float2 att = make_float2(0.f, 0.f);
        #pragma unroll
        for (int k = 0; k < KNB; k++) {
            float4 pt = sPts[w*16 + k];
            int idx = __float_as_int(pt.w);
            float pf0 = fmaxf(fmaf(cz[0], pt.z, fmaf(cy[0], pt.y, fmaf(cx[0], pt.x, cb[0]))), 0.f);
            float pf1 = fmaxf(fmaf(cz[1], pt.z, fmaf(cy[1], pt.y, fmaf(cx[1], pt.x, cb[1]))), 0.f);
            float2 vg = make_float2(0.f, 0.f);
            if (idx >= 0) vg = *(const float2*)(g_v + (size_t)idx*DIM + d0);
            att.x = fmaf(vg.x + pf0, wq[k].x * inv.x, att.x);
            att.y = fmaf(vg.y + pf1, wq[k].y * inv.y, att.y);
        }
        *(float2*)(out + (size_t)n*DIM + d0) = att;
    }
}

// ---------------- launch ----------------
extern "C" void kernel_launch(void* const* d_in, const int* in_sizes, int n_in,
                              void* d_out, int out_size)
{
    const float* points  = (const float*)d_in[0];
    const int*   nbrs    = (const int*)  d_in[1];
    const float* feats   = (const float*)d_in[2];
    const float* q_w = (const float*)d_in[3];  const float* q_b = (const float*)d_in[4];
    const float* k_w = (const float*)d_in[5];  const float* k_b = (const float*)d_in[6];
    const float* v_w = (const float*)d_in[7];  const float* v_b = (const float*)d_in[8];
    const float* p_w = (const float*)d_in[9];  const float* p_b = (const float*)d_in[10];
    const float* p_gamma = (const float*)d_in[11]; const float* p_beta = (const float*)d_in[12];
    const float* w_w = (const float*)d_in[13]; const float* w_b = (const float*)d_in[14];
    const float* w_gamma = (const float*)d_in[15]; const float* w_beta = (const float*)d_in[16];
    float* out = (float*)d_out;

    const int FE_SMEM = (12288 + 2304 + 192) * 4;
    cudaFuncSetAttribute(frontend_kernel, cudaFuncAttributeMaxDynamicSharedMemorySize, FE_SMEM);
    cudaFuncSetAttribute(passC_kernel,    cudaFuncAttributeMaxDynamicSharedMemorySize, PC_SMEM);

    zero_acc_kernel<<<1, 256>>>();
    frontend_kernel<<<FE_BLOCKS, FE_THREADS, FE_SMEM>>>(
        feats, q_w, q_b, k_w, k_b, v_w, v_b, points, nbrs, p_w, p_b);
    finalize_kernel<<<1, 64>>>(p_gamma, p_beta, 0);
    passC_kernel<<<PC_BLOCKS, 128, PC_SMEM>>>(points, nbrs, p_w, p_b, w_w, w_b);
    finalize_kernel<<<1, 64>>>(w_gamma, w_beta, 128);
    passD_kernel<<<PD_BLOCKS, PD_THREADS>>>(points, nbrs, p_w, p_b, out);
}

// round 13
// speedup vs baseline: 1.4005x; 1.4005x over previous
#include <cuda_runtime.h>
#include <cuda_bf16.h>
#include <math.h>
#include <stdint.h>

#define NPTS 100000
#define KNB  16
#define DIM  64
#define NK   (NPTS*KNB)

typedef unsigned long long ull;

// ---------------- f32x2 helpers (frontend) ----------------
__device__ __forceinline__ ull ffma2(ull a, ull b, ull c) {
    ull d;
    asm("fma.rn.f32x2 %0, %1, %2, %3;" : "=l"(d) : "l"(a), "l"(b), "l"(c));
    return d;
}
__device__ __forceinline__ void unpack2(ull p, float& lo, float& hi) {
    asm("mov.b64 {%0, %1}, %2;" : "=f"(lo), "=f"(hi) : "l"(p));
}

// ---------------- mma helpers ----------------
__device__ __forceinline__ uint32_t smem_u32(const void* p) {
    uint32_t a;
    asm("{ .reg .u64 t; cvta.to.shared.u64 t, %1; cvt.u32.u64 %0, t; }" : "=r"(a) : "l"(p));
    return a;
}
__device__ __forceinline__ void ldsm_x4(uint32_t* r, uint32_t addr) {
    asm volatile("ldmatrix.sync.aligned.m8n8.x4.shared.b16 {%0,%1,%2,%3}, [%4];"
        : "=r"(r[0]), "=r"(r[1]), "=r"(r[2]), "=r"(r[3]) : "r"(addr));
}
__device__ __forceinline__ void mma16816(float* d, const uint32_t* a, const uint32_t* b) {
    asm volatile("mma.sync.aligned.m16n8k16.row.col.f32.bf16.bf16.f32 "
        "{%0,%1,%2,%3}, {%4,%5,%6,%7}, {%8,%9}, {%0,%1,%2,%3};"
        : "+f"(d[0]), "+f"(d[1]), "+f"(d[2]), "+f"(d[3])
        : "r"(a[0]), "r"(a[1]), "r"(a[2]), "r"(a[3]), "r"(b[0]), "r"(b[1]));
}
#define SWZ(o) ((o) ^ (((o) >> 3) & 0x70))

// ---------------- scratch ----------------
__device__ float  g_q[(size_t)NPTS*DIM];
__device__ float  g_k[(size_t)NPTS*DIM];
__device__ float  g_v[(size_t)NPTS*DIM];
__device__ float  g_wpre[(size_t)NPTS*KNB*DIM];
__device__ double g_acc[256];
__device__ float  g_stats[256];

__global__ void zero_acc_kernel() {
    if (threadIdx.x < 256) g_acc[threadIdx.x] = 0.0;
}

// ---------------- frontend: qkv GEMM + BN1 stats (R10 version — known good) ----
#define FE_THREADS   192
#define QKV_BLOCKS   304
#define STATS_BLOCKS 140
#define FE_BLOCKS    (QKV_BLOCKS + STATS_BLOCKS)

__global__ void __launch_bounds__(FE_THREADS) frontend_kernel(
    const float* __restrict__ feats,
    const float* __restrict__ qw, const float* __restrict__ qb,
    const float* __restrict__ kw, const float* __restrict__ kb,
    const float* __restrict__ vw, const float* __restrict__ vb,
    const float* __restrict__ points,
    const int*   __restrict__ nb,
    const float* __restrict__ pw,
    const float* __restrict__ pb)
{
    extern __shared__ float sm[];
    const int tid = threadIdx.x;

    if (blockIdx.x < QKV_BLOCKS) {
        float* sW    = sm;
        float* sFdup = sm + 12288;
        float* sB    = sm + 12288 + 2304;

        for (int i = tid; i < 192*64; i += FE_THREADS) {
            int c = i % 192, e = i / 192;
            const float* src = (c < 64) ? qw : (c < 128) ? kw : vw;
            sW[e*192 + c] = __ldg(src + (c & 63)*DIM + e);
        }
        if (tid < 192) {
            const float* src = (tid < 64) ? qb : (tid < 128) ? kb : vb;
            sB[tid] = __ldg(src + (tid & 63));
        }
        __syncthreads();

        const int c4 = tid % 48;
        const int pb4 = tid / 48;
        const int c = 4*c4;
        const ull b0 = *(const ull*)&sB[c];
        const ull b1 = *(const ull*)&sB[c+2];
        float* dst = (c < 64) ? g_q : (c < 128) ? g_k : g_v;
        const int cc = c & 63;

        for (int tile = blockIdx.x; tile < NPTS/16; tile += QKV_BLOCKS) {
            const int n0 = tile*16;
            __syncthreads();
            for (int i = tid; i < 16*64; i += FE_THREADS) {
                int e = i & 63, p = i >> 6;
                float f = __ldg(feats + (size_t)(n0+p)*DIM + e);
                *(float2*)&sFdup[e*36 + 2*p] = make_float2(f, f);
            }
            __syncthreads();

            ull acc[4][2];
            #pragma unroll
            for (int p = 0; p < 4; p++) { acc[p][0] = b0; acc[p][1] = b1; }

            #pragma unroll
            for (int e = 0; e < 64; e++) {
                ulonglong2 wv  = *(const ulonglong2*)&sW[e*192 + c];
                ulonglong2 f01 = *(const ulonglong2*)&sFdup[e*36 + 8*pb4];
                ulonglong2 f23 = *(const ulonglong2*)&sFdup[e*36 + 8*pb4 + 4];
                acc[0][0] = ffma2(f01.x, wv.x, acc[0][0]);
                acc[0][1] = ffma2(f01.x, wv.y, acc[0][1]);
                acc[1][0] = ffma2(f01.y, wv.x, acc[1][0]);
                acc[1][1] = ffma2(f01.y, wv.y, acc[1][1]);
                acc[2][0] = ffma2(f23.x, wv.x, acc[2][0]);
                acc[2][1] = ffma2(f23.x, wv.y, acc[2][1]);
                acc[3][0] = ffma2(f23.y, wv.x, acc[3][0]);
                acc[3][1] = ffma2(f23.y, wv.y, acc[3][1]);
            }

            const int nb0 = n0 + 4*pb4;
            #pragma unroll
            for (int p = 0; p < 4; p++) {
                float4 r;
                unpack2(acc[p][0], r.x, r.y);
                unpack2(acc[p][1], r.z, r.w);
                *(float4*)(dst + (size_t)(nb0+p)*DIM + cc) = r;
            }
        }
    } else {
        const int quad = tid & 15;
        const int slot = tid >> 4;
        const int d0   = 4*quad;

        float w[12], br[4];
        #pragma unroll
        for (int j = 0; j < 4; j++) {
            w[j*3+0] = __ldg(pw + (d0+j)*3 + 0);
            w[j*3+1] = __ldg(pw + (d0+j)*3 + 1);
            w[j*3+2] = __ldg(pw + (d0+j)*3 + 2);
            br[j]    = __ldg(pb + d0 + j);
        }

        float s[4] = {0,0,0,0}, sq[4] = {0,0,0,0};
        const int bid = blockIdx.x - QKV_BLOCKS;
        for (int r = bid*12 + slot; r < NK; r += STATS_BLOCKS*12) {
            int idx = __ldg(nb + r);
            float x, y, z;
            if (idx >= NPTS) { x = y = z = 1e6f; }
            else {
                x = __ldg(points + (size_t)idx*3    );
                y = __ldg(points + (size_t)idx*3 + 1);
                z = __ldg(points + (size_t)idx*3 + 2);
            }
            #pragma unroll
            for (int j = 0; j < 4; j++) {
                float v = fmaf(w[j*3+2], z, fmaf(w[j*3+1], y, fmaf(w[j*3+0], x, br[j])));
                s[j] += v;
                sq[j] = fmaf(v, v, sq[j]);
            }
        }

        float* sred = sm;
        #pragma unroll
        for (int j = 0; j < 4; j++) {
            sred[tid*8 + j]     = s[j];
            sred[tid*8 + 4 + j] = sq[j];
        }
        __syncthreads();
        if (tid < 64) {
            int tq = tid >> 2, j = tid & 3;
            double ds = 0.0, dsq = 0.0;
            #pragma unroll
            for (int sl = 0; sl < 12; sl++) {
                ds  += (double)sred[(sl*16 + tq)*8 + j];
                dsq += (double)sred[(sl*16 + tq)*8 + 4 + j];
            }
            atomicAdd(&g_acc[tid],      ds);
            atomicAdd(&g_acc[64 + tid], dsq);
        }
    }
}

// ---------------- finalize ----------------
__global__ void finalize_kernel(const float* __restrict__ gamma,
                                const float* __restrict__ beta, int base)
{
    int d = threadIdx.x;
    if (d < 64) {
        double cnt = (double)NK;
        double m   = g_acc[base + d] / cnt;
        double var = g_acc[base + 64 + d] / cnt - m*m;
        double rs  = 1.0 / sqrt(var + 1e-5);
        double g   = (double)__ldg(gamma + d);
        g_stats[base + d]      = (float)(rs * g);
        g_stats[base + 64 + d] = (float)((double)__ldg(beta + d) - m * rs * g);
    }
}

// ---------------- pass C: mma.sync bf16 2-term split GEMM (uint4 A-stores) ----
#define OFF_BHI  0
#define OFF_BLO  8192
#define OFF_AHI  16384
#define OFF_ALO  32768
#define OFF_Q    49152
#define OFF_C    51200
#define OFF_WB   52224
#define PC_SMEM  52480
#define PC_BLOCKS 444

__global__ void __launch_bounds__(128) passC_kernel(
    const float* __restrict__ points,
    const int*   __restrict__ nb,
    const float* __restrict__ pw,
    const float* __restrict__ pb,
    const float* __restrict__ ww,
    const float* __restrict__ wb)
{
    extern __shared__ __align__(1024) char smc[];
    const uint32_t sb = smem_u32(smc);
    const int tid  = threadIdx.x;
    const int wid  = tid >> 5;
    const int lane = tid & 31;

    float* sQ  = (float*)(smc + OFF_Q);
    float* sC  = (float*)(smc + OFF_C);
    float* sWb = (float*)(smc + OFF_WB);

    for (int i = tid; i < 4096; i += 128) {
        int d = i >> 6, e = i & 63;
        float v = __ldg(ww + d*DIM + e);
        __nv_bfloat16 h = __float2bfloat16(v);
        float lo = v - __bfloat162float(h);
        uint32_t sw = SWZ((uint32_t)(d*128 + e*2));
        *(__nv_bfloat16*)(smc + OFF_BHI + sw) = h;
        *(__nv_bfloat16*)(smc + OFF_BLO + sw) = __float2bfloat16(lo);
    }
    if (tid < 64) {
        float sc = g_stats[tid], sh = g_stats[64 + tid];
        sC[0*64 + tid] = sc * __ldg(pw + tid*3    );
        sC[1*64 + tid] = sc * __ldg(pw + tid*3 + 1);
        sC[2*64 + tid] = sc * __ldg(pw + tid*3 + 2);
        sC[3*64 + tid] = fmaf(sc, __ldg(pb + tid), sh);
        sWb[tid] = __ldg(wb + tid);
    }
    __syncthreads();

    const int m  = tid;
    const int p  = m >> 4;
    const int kk = m & 15;

    float2 s[8], q2[8];
    #pragma unroll
    for (int nt = 0; nt < 8; nt++) { s[nt] = make_float2(0.f,0.f); q2[nt] = make_float2(0.f,0.f); }

    const int c4 = 2*(lane & 3);
    const int rb = wid*32 + (lane >> 2);

    for (int tile = blockIdx.x; tile < NPTS/8; tile += PC_BLOCKS) {
        __syncwarp();

        {
            int pp = tid >> 4, e4 = (tid & 15) * 4;
            *(float4*)&sQ[pp*64 + e4] =
                *(const float4*)(g_q + (size_t)(tile*8 + pp)*DIM + e4);
        }
        __syncwarp();

        const int n = tile*8 + p;
        int idx = __ldg(nb + (size_t)n*KNB + kk);
        bool pad = (idx >= NPTS);
        float x, y, z;
        if (pad) { x = y = z = 1e6f; }
        else {
            x = __ldg(points + (size_t)idx*3    );
            y = __ldg(points + (size_t)idx*3 + 1);
            z = __ldg(points + (size_t)idx*3 + 2);
        }
        const float* krow = g_k + (size_t)(pad ? 0 : idx)*DIM;

        // build A row m: 8 channels per iteration, uint4 stores
        #pragma unroll
        for (int e0 = 0; e0 < 64; e0 += 8) {
            float4 kgA = pad ? make_float4(0.f,0.f,0.f,0.f) : *(const float4*)(krow + e0);
            float4 kgB = pad ? make_float4(0.f,0.f,0.f,0.f) : *(const float4*)(krow + e0 + 4);
            float win[8];
            #pragma unroll
            for (int half = 0; half < 2; half++) {
                const int e = e0 + 4*half;
                float4 kg = half ? kgB : kgA;
                float4 q4 = *(const float4*)&sQ[p*64 + e];
                float4 cx = *(const float4*)&sC[0*64 + e];
                float4 cy = *(const float4*)&sC[1*64 + e];
                float4 cz = *(const float4*)&sC[2*64 + e];
                float4 cb = *(const float4*)&sC[3*64 + e];
                win[4*half+0] = fmaf(kg.x, q4.x, fmaxf(fmaf(cz.x, z, fmaf(cy.x, y, fmaf(cx.x, x, cb.x))), 0.f));
                win[4*half+1] = fmaf(kg.y, q4.y, fmaxf(fmaf(cz.y, z, fmaf(cy.y, y, fmaf(cx.y, x, cb.y))), 0.f));
                win[4*half+2] = fmaf(kg.z, q4.z, fmaxf(fmaf(cz.z, z, fmaf(cy.z, y, fmaf(cx.z, x, cb.z))), 0.f));
                win[4*half+3] = fmaf(kg.w, q4.w, fmaxf(fmaf(cz.w, z, fmaf(cy.w, y, fmaf(cx.w, x, cb.w))), 0.f));
            }

            __nv_bfloat16 h[8]; float lo[8];
            #pragma unroll
            for (int j = 0; j < 8; j++) {
                h[j]  = __float2bfloat16(win[j]);
                lo[j] = win[j] - __bfloat162float(h[j]);
            }
            uint32_t sw = SWZ((uint32_t)(m*128 + e0*2));
            uint4 hv, lv;
            {
                __nv_bfloat162 t0 = __halves2bfloat162(h[0], h[1]);
                __nv_bfloat162 t1 = __halves2bfloat162(h[2], h[3]);
                __nv_bfloat162 t2 = __halves2bfloat162(h[4], h[5]);
                __nv_bfloat162 t3 = __halves2bfloat162(h[6], h[7]);
                hv = make_uint4(*(uint32_t*)&t0, *(uint32_t*)&t1,
                                *(uint32_t*)&t2, *(uint32_t*)&t3);
                __nv_bfloat162 u0 = __floats2bfloat162_rn(lo[0], lo[1]);
                __nv_bfloat162 u1 = __floats2bfloat162_rn(lo[2], lo[3]);
                __nv_bfloat162 u2 = __floats2bfloat162_rn(lo[4], lo[5]);
                __nv_bfloat162 u3 = __floats2bfloat162_rn(lo[6], lo[7]);
                lv = make_uint4(*(uint32_t*)&u0, *(uint32_t*)&u1,
                                *(uint32_t*)&u2, *(uint32_t*)&u3);
            }
            *(uint4*)(smc + OFF_AHI + sw) = hv;
            *(uint4*)(smc + OFF_ALO + sw) = lv;
        }
        __syncwarp();

        float acc[2][8][4];
        #pragma unroll
        for (int mt = 0; mt < 2; mt++)
            #pragma unroll
            for (int nt = 0; nt < 8; nt++)
                #pragma unroll
                for (int r = 0; r < 4; r++) acc[mt][nt][r] = 0.f;

        #pragma unroll
        for (int ks = 0; ks < 4; ks++) {
            uint32_t ah[2][4], al[2][4];
            #pragma unroll
            for (int mt = 0; mt < 2; mt++) {
                uint32_t off = SWZ((uint32_t)((wid*32 + mt*16 + (lane & 15))*128
                                              + ks*32 + ((lane >> 4) << 4)));
                ldsm_x4(ah[mt], sb + OFF_AHI + off);
                ldsm_x4(al[mt], sb + OFF_ALO + off);
            }
            uint32_t bh[4][4], bl[4][4];
            #pragma unroll
            for (int np = 0; np < 4; np++) {
                int nrow = np*16 + (lane & 7) + ((lane >> 4) << 3);
                uint32_t off = SWZ((uint32_t)(nrow*128 + ks*32 + (((lane >> 3) & 1) << 4)));
                ldsm_x4(bh[np], sb + OFF_BHI + off);
                ldsm_x4(bl[np], sb + OFF_BLO + off);
            }
            #pragma unroll
            for (int mt = 0; mt < 2; mt++)
                #pragma unroll
                for (int np = 0; np < 4; np++) {
                    mma16816(acc[mt][2*np  ], ah[mt], &bh[np][0]);
                    mma16816(acc[mt][2*np  ], al[mt], &bh[np][0]);
                    mma16816(acc[mt][2*np  ], ah[mt], &bl[np][0]);
                    mma16816(acc[mt][2*np+1], ah[mt], &bh[np][2]);
                    mma16816(acc[mt][2*np+1], al[mt], &bh[np][2]);
                    mma16816(acc[mt][2*np+1], ah[mt], &bl[np][2]);
                }
        }

        #pragma unroll
        for (int nt = 0; nt < 8; nt++) {
            float bx = sWb[nt*8 + c4];
            float by = sWb[nt*8 + c4 + 1];
            #pragma unroll
            for (int mt = 0; mt < 2; mt++) {
                float v0 = acc[mt][nt][0] + bx;
                float v1 = acc[mt][nt][1] + by;
                float v2 = acc[mt][nt][2] + bx;
                float v3 = acc[mt][nt][3] + by;
                size_t r0 = (size_t)(tile*128 + rb + mt*16)*64 + nt*8 + c4;
                *(float2*)(g_wpre + r0)        = make_float2(v0, v1);
                *(float2*)(g_wpre + r0 + 512)  = make_float2(v2, v3);
                s[nt].x += v0 + v2;  s[nt].y += v1 + v3;
                q2[nt].x = fmaf(v0, v0, fmaf(v2, v2, q2[nt].x));
                q2[nt].y = fmaf(v1, v1, fmaf(v3, v3, q2[nt].y));
            }
        }
    }

    #pragma unroll
    for (int nt = 0; nt < 8; nt++) {
        #pragma unroll
        for (int d = 4; d <= 16; d <<= 1) {
            s[nt].x  += __shfl_xor_sync(0xFFFFFFFFu, s[nt].x,  d);
            s[nt].y  += __shfl_xor_sync(0xFFFFFFFFu, s[nt].y,  d);
            q2[nt].x += __shfl_xor_sync(0xFFFFFFFFu, q2[nt].x, d);
            q2[nt].y += __shfl_xor_sync(0xFFFFFFFFu, q2[nt].y, d);
        }
    }
    if ((lane >> 2) == 0) {
        #pragma unroll
        for (int nt = 0; nt < 8; nt++) {
            int c = nt*8 + c4;
            atomicAdd(&g_acc[128 + c],     (double)s[nt].x);
            atomicAdd(&g_acc[128 + c + 1], (double)s[nt].y);
            atomicAdd(&g_acc[192 + c],     (double)q2[nt].x);
            atomicAdd(&g_acc[192 + c + 1], (double)q2[nt].y);
        }
    }
}

// ---------------- pass D: warp-per-point, 2 channels/lane, no block syncs ------
#define PD_THREADS 256
#define PD_BLOCKS  1184
__global__ void __launch_bounds__(PD_THREADS) passD_kernel(
    const float* __restrict__ points,
    const int*   __restrict__ nb,
    const float* __restrict__ pw,
    const float* __restrict__ pb,
    float* __restrict__ out)
{
    __shared__ float4 sPts[8*16];

    const int tid  = threadIdx.x;
    const int w    = tid >> 5;
    const int lane = tid & 31;
    const int d0   = 2*lane;

    float cx[2], cy[2], cz[2], cb[2], sc2[2], sh2[2];
    #pragma unroll
    for (int j = 0; j < 2; j++) {
        float sc = g_stats[d0 + j], sh = g_stats[64 + d0 + j];
        cx[j] = sc * __ldg(pw + (d0+j)*3    );
        cy[j] = sc * __ldg(pw + (d0+j)*3 + 1);
        cz[j] = sc * __ldg(pw + (d0+j)*3 + 2);
        cb[j] = fmaf(sc, __ldg(pb + d0 + j), sh);
        sc2[j] = g_stats[128 + d0 + j];
        sh2[j] = g_stats[192 + d0 + j];
    }

    for (int n = blockIdx.x*8 + w; n < NPTS; n += PD_BLOCKS*8) {
        __syncwarp();
        if (lane < KNB) {
            int idx = __ldg(nb + (size_t)n*KNB + lane);
            float4 pt;
            if (idx >= NPTS) {
                pt = make_float4(1e6f, 1e6f, 1e6f, __int_as_float(-1));
            } else {
                pt.x = __ldg(points + (size_t)idx*3    );
                pt.y = __ldg(points + (size_t)idx*3 + 1);
                pt.z = __ldg(points + (size_t)idx*3 + 2);
                pt.w = __int_as_float(idx);
            }
            sPts[w*16 + lane] = pt;
        }
        __syncwarp();

        float2 wq[KNB];
        #pragma unroll
        for (int k = 0; k < KNB; k++) {
            float2 v = *(const float2*)(g_wpre + ((size_t)n*KNB + k)*DIM + d0);
            wq[k].x = fmaxf(fmaf(v.x, sc2[0], sh2[0]), 0.f);
            wq[k].y = fmaxf(fmaf(v.y, sc2[1], sh2[1]), 0.f);
        }
        float2 mx = wq[0];
        #pragma unroll
        for (int k = 1; k < KNB; k++) {
            mx.x = fmaxf(mx.x, wq[k].x);
            mx.y = fmaxf(mx.y, wq[k].y);
        }
        float2 se = make_float2(0.f, 0.f);
        #pragma unroll
        for (int k = 0; k < KNB; k++) {
            wq[k].x = __expf(wq[k].x - mx.x); se.x += wq[k].x;
            wq[k].y = __expf(wq[k].y - mx.y); se.y += wq[k].y;
        }
        float2 inv;
        inv.x = __fdividef(1.f, se.x);
        inv.y = __fdividef(1.f, se.y);

        float2 att = make_float2(0.f, 0.f);
        #pragma unroll
        for (int k = 0; k < KNB; k++) {
            float4 pt = sPts[w*16 + k];
            int idx = __float_as_int(pt.w);
            float pf0 = fmaxf(fmaf(cz[0], pt.z, fmaf(cy[0], pt.y, fmaf(cx[0], pt.x, cb[0]))), 0.f);
            float pf1 = fmaxf(fmaf(cz[1], pt.z, fmaf(cy[1], pt.y, fmaf(cx[1], pt.x, cb[1]))), 0.f);
            float2 vg = make_float2(0.f, 0.f);
            if (idx >= 0) vg = *(const float2*)(g_v + (size_t)idx*DIM + d0);
            att.x = fmaf(vg.x + pf0, wq[k].x * inv.x, att.x);
            att.y = fmaf(vg.y + pf1, wq[k].y * inv.y, att.y);
        }
        *(float2*)(out + (size_t)n*DIM + d0) = att;
    }
}

// ---------------- launch ----------------
extern "C" void kernel_launch(void* const* d_in, const int* in_sizes, int n_in,
                              void* d_out, int out_size)
{
    const float* points  = (const float*)d_in[0];
    const int*   nbrs    = (const int*)  d_in[1];
    const float* feats   = (const float*)d_in[2];
    const float* q_w = (const float*)d_in[3];  const float* q_b = (const float*)d_in[4];
    const float* k_w = (const float*)d_in[5];  const float* k_b = (const float*)d_in[6];
    const float* v_w = (const float*)d_in[7];  const float* v_b = (const float*)d_in[8];
    const float* p_w = (const float*)d_in[9];  const float* p_b = (const float*)d_in[10];
    const float* p_gamma = (const float*)d_in[11]; const float* p_beta = (const float*)d_in[12];
    const float* w_w = (const float*)d_in[13]; const float* w_b = (const float*)d_in[14];
    const float* w_gamma = (const float*)d_in[15]; const float* w_beta = (const float*)d_in[16];
    float* out = (float*)d_out;

    const int FE_SMEM = (12288 + 2304 + 192) * 4;
    cudaFuncSetAttribute(frontend_kernel, cudaFuncAttributeMaxDynamicSharedMemorySize, FE_SMEM);
    cudaFuncSetAttribute(passC_kernel,    cudaFuncAttributeMaxDynamicSharedMemorySize, PC_SMEM);

    zero_acc_kernel<<<1, 256>>>();
    frontend_kernel<<<FE_BLOCKS, FE_THREADS, FE_SMEM>>>(
        feats, q_w, q_b, k_w, k_b, v_w, v_b, points, nbrs, p_w, p_b);
    finalize_kernel<<<1, 64>>>(p_gamma, p_beta, 0);
    passC_kernel<<<PC_BLOCKS, 128, PC_SMEM>>>(points, nbrs, p_w, p_b, w_w, w_b);
    finalize_kernel<<<1, 64>>>(w_gamma, w_beta, 128);
    passD_kernel<<<PD_BLOCKS, PD_THREADS>>>(points, nbrs, p_w, p_b, out);
}